// round 5
// baseline (speedup 1.0000x reference)
#include <cuda_runtime.h>
#include <cuda_bf16.h>
#include <math.h>
#include <stdint.h>

// Problem constants
#define BATCH 4
#define SEQ   2048
#define EMBED 1024
#define HSZ   1024
#define QKV3  3072
#define BS    (BATCH*SEQ)

typedef __nv_bfloat16 bf16;

// Scratch (device globals -- no allocation allowed)
__device__ bf16  g_xh[(size_t)BS * EMBED];
__device__ bf16  g_xl[(size_t)BS * EMBED];
__device__ bf16  g_wqh[(size_t)QKV3 * EMBED];
__device__ bf16  g_wql[(size_t)QKV3 * EMBED];
__device__ bf16  g_wph[(size_t)EMBED * HSZ];
__device__ bf16  g_wpl[(size_t)EMBED * HSZ];
__device__ bf16  g_qkvh[(size_t)BS * QKV3];
__device__ bf16  g_qkvl[(size_t)BS * QKV3];
__device__ float g_scores[(size_t)BATCH * SEQ * SEQ];
__device__ bf16  g_ph[(size_t)BATCH * SEQ * SEQ];
__device__ bf16  g_pl[(size_t)BATCH * SEQ * SEQ];
__device__ bf16  g_vTh[(size_t)BATCH * HSZ * SEQ];
__device__ bf16  g_vTl[(size_t)BATCH * HSZ * SEQ];
__device__ bf16  g_oh[(size_t)BATCH * SEQ * HSZ];
__device__ bf16  g_ol[(size_t)BATCH * SEQ * HSZ];
__device__ bf16  g_oTh[(size_t)BATCH * HSZ * SEQ];
__device__ bf16  g_oTl[(size_t)BATCH * HSZ * SEQ];

// ---------------------------------------------------------------------------
__device__ __forceinline__ uint32_t smem_u32(const void* p) {
    uint32_t a;
    asm("{ .reg .u64 t; cvta.to.shared.u64 t, %1; cvt.u32.u64 %0, t; }"
        : "=r"(a) : "l"(p));
    return a;
}
__device__ __forceinline__ void cp16(uint32_t dst, const void* src) {
    asm volatile("cp.async.cg.shared.global [%0], [%1], 16;"
                 :: "r"(dst), "l"(src));
}
__device__ __forceinline__ void ldsm4(uint32_t* r, uint32_t addr) {
    asm volatile("ldmatrix.sync.aligned.m8n8.x4.shared.b16 {%0,%1,%2,%3}, [%4];"
                 : "=r"(r[0]), "=r"(r[1]), "=r"(r[2]), "=r"(r[3]) : "r"(addr));
}
__device__ __forceinline__ void mma16816(float* c, const uint32_t* a,
                                         const uint32_t* b) {
    asm volatile(
        "mma.sync.aligned.m16n8k16.row.col.f32.bf16.bf16.f32 "
        "{%0,%1,%2,%3}, {%4,%5,%6,%7}, {%8,%9}, {%0,%1,%2,%3};"
        : "+f"(c[0]), "+f"(c[1]), "+f"(c[2]), "+f"(c[3])
        : "r"(a[0]), "r"(a[1]), "r"(a[2]), "r"(a[3]), "r"(b[0]), "r"(b[1]));
}

// ---------------------------------------------------------------------------
// bf16x3 NT GEMM: C[m,n] = alpha * sum_k (Ah+Al)[m,k]*(Bh+Bl)[n,k]  (3 MMAs)
// BM=128, BN=256, BK=64. 512 threads = 16 warps (4m x 4n); warp tile 32x64.
// 2-stage cp.async pipeline (96KB/stage, 192KB total) -> 16 warps/SM.
// MODE 0: fp32 out; 1: fp32+bias; 2: split bf16 out (Ch,Cl)
// ---------------------------------------------------------------------------
template <int MODE>
__global__ __launch_bounds__(512, 1) void tc_gemm(
    const bf16* __restrict__ Ah, const bf16* __restrict__ Al,
    const bf16* __restrict__ Bh, const bf16* __restrict__ Bl,
    float* __restrict__ C, bf16* __restrict__ Ch, bf16* __restrict__ Cl,
    const float* __restrict__ bias,
    int K, int lda, int ldb, int ldc,
    long long sA, long long sB, long long sC, float alpha)
{
    constexpr uint32_t A_LIMB = 16384u;       // 128 rows x 128B
    constexpr uint32_t B_OFF  = 32768u;
    constexpr uint32_t B_LIMB = 32768u;       // 256 rows x 128B
    constexpr uint32_t STAGE  = 98304u;

    extern __shared__ char dsm[];
    const uint32_t base = smem_u32(dsm);

    const int tid = threadIdx.x;
    const int wid = tid >> 5, lane = tid & 31;
    const int wm = wid >> 2, wn = wid & 3;           // 4 x 4 warps
    const int gid = lane >> 2, tig = lane & 3;

    Ah += (long long)blockIdx.z * sA;  Al += (long long)blockIdx.z * sA;
    Bh += (long long)blockIdx.z * sB;  Bl += (long long)blockIdx.z * sB;
    const long long co = (long long)blockIdx.z * sC;
    const int m0 = blockIdx.y * 128;
    const int n0 = blockIdx.x * 256;

    // ldmatrix per-lane row/chunk decode
    const int rAl = lane & 15,                       cA16 = (lane >> 4) << 4;
    const int rBl = (lane & 7) | ((lane >> 4) << 3), cB16 = ((lane >> 3) & 1) << 4;

    uint32_t rbA[2], swA[2], rbB[4], swB[4];
#pragma unroll
    for (int mt = 0; mt < 2; mt++) {
        int row = wm * 32 + mt * 16 + rAl;
        rbA[mt] = (uint32_t)row << 7;
        swA[mt] = (uint32_t)(row & 7) << 4;
    }
#pragma unroll
    for (int np = 0; np < 4; np++) {
        int row = wn * 64 + np * 16 + rBl;
        rbB[np] = (uint32_t)row << 7;
        swB[np] = (uint32_t)(row & 7) << 4;
    }

    float c[2][8][4];
#pragma unroll
    for (int mt = 0; mt < 2; mt++)
#pragma unroll
        for (int nt = 0; nt < 8; nt++)
#pragma unroll
            for (int i = 0; i < 4; i++) c[mt][nt][i] = 0.f;

    const int NIT = K >> 6;

    auto load_stage = [&](int it, int s) {
        const uint32_t st = base + (uint32_t)s * STAGE;
        const int c0 = it << 6;
#pragma unroll
        for (int i = 0; i < 2; i++) {              // A: 128 rows x 8 cp16
            int idx = tid + i * 512;
            int r = idx >> 3, ch = idx & 7;
            uint32_t off = ((uint32_t)r << 7) + (((uint32_t)ch << 4) ^ ((uint32_t)(r & 7) << 4));
            cp16(st + off,          Ah + (size_t)(m0 + r) * lda + c0 + ch * 8);
            cp16(st + A_LIMB + off, Al + (size_t)(m0 + r) * lda + c0 + ch * 8);
        }
#pragma unroll
        for (int i = 0; i < 4; i++) {              // B: 256 rows x 8 cp16
            int idx = tid + i * 512;
            int r = idx >> 3, ch = idx & 7;
            uint32_t off = ((uint32_t)r << 7) + (((uint32_t)ch << 4) ^ ((uint32_t)(r & 7) << 4));
            cp16(st + B_OFF + off,          Bh + (size_t)(n0 + r) * ldb + c0 + ch * 8);
            cp16(st + B_OFF + B_LIMB + off, Bl + (size_t)(n0 + r) * ldb + c0 + ch * 8);
        }
        asm volatile("cp.async.commit_group;" ::: "memory");
    };

    load_stage(0, 0);
    load_stage(1, 1);

#pragma unroll 1
    for (int it = 0; it < NIT; it++) {
        asm volatile("cp.async.wait_group 1;" ::: "memory");
        __syncthreads();

        const uint32_t st = base + (uint32_t)(it & 1) * STAGE;
#pragma unroll
        for (int ks = 0; ks < 4; ks++) {
            const uint32_t kb = (uint32_t)ks << 5;
            uint32_t ah[2][4], al[2][4];
#pragma unroll
            for (int mt = 0; mt < 2; mt++) {
                uint32_t a = st + rbA[mt] + ((kb + cA16) ^ swA[mt]);
                ldsm4(ah[mt], a);
                ldsm4(al[mt], a + A_LIMB);
            }
#pragma unroll
            for (int np = 0; np < 4; np++) {
                uint32_t bh[4], bl[4];
                uint32_t b = st + B_OFF + rbB[np] + ((kb + cB16) ^ swB[np]);
                ldsm4(bh, b);
                ldsm4(bl, b + B_LIMB);
#pragma unroll
                for (int mt = 0; mt < 2; mt++) {
#pragma unroll
                    for (int h = 0; h < 2; h++) {
                        float* cc = c[mt][np * 2 + h];
                        mma16816(cc, ah[mt], bh + 2 * h);
                        mma16816(cc, ah[mt], bl + 2 * h);
                        mma16816(cc, al[mt], bh + 2 * h);
                    }
                }
            }
        }
        __syncthreads();
        if (it + 2 < NIT) load_stage(it + 2, it & 1);
        else asm volatile("cp.async.commit_group;" ::: "memory");
    }

    // Epilogue
#pragma unroll
    for (int mt = 0; mt < 2; mt++) {
#pragma unroll
        for (int nt = 0; nt < 8; nt++) {
            int m = m0 + wm * 32 + mt * 16 + gid;
            int n = n0 + wn * 64 + nt * 8 + tig * 2;
            float v0 = alpha * c[mt][nt][0];
            float v1 = alpha * c[mt][nt][1];
            float v2 = alpha * c[mt][nt][2];
            float v3 = alpha * c[mt][nt][3];
            if (MODE == 1) {
                float b0 = bias[n], b1 = bias[n + 1];
                v0 += b0; v1 += b1; v2 += b0; v3 += b1;
            }
            if (MODE == 2) {
                bf16 h0 = __float2bfloat16(v0);
                bf16 h1 = __float2bfloat16(v1);
                bf16 h2 = __float2bfloat16(v2);
                bf16 h3 = __float2bfloat16(v3);
                bf16 l0 = __float2bfloat16(v0 - __bfloat162float(h0));
                bf16 l1 = __float2bfloat16(v1 - __bfloat162float(h1));
                bf16 l2 = __float2bfloat16(v2 - __bfloat162float(h2));
                bf16 l3 = __float2bfloat16(v3 - __bfloat162float(h3));
                __nv_bfloat162 hh0{h0, h1}, hh1{h2, h3};
                __nv_bfloat162 ll0{l0, l1}, ll1{l2, l3};
                *(__nv_bfloat162*)&Ch[co + (size_t)m * ldc + n]       = hh0;
                *(__nv_bfloat162*)&Ch[co + (size_t)(m + 8) * ldc + n] = hh1;
                *(__nv_bfloat162*)&Cl[co + (size_t)m * ldc + n]       = ll0;
                *(__nv_bfloat162*)&Cl[co + (size_t)(m + 8) * ldc + n] = ll1;
            } else {
                *(float2*)&C[co + (size_t)m * ldc + n]       = make_float2(v0, v1);
                *(float2*)&C[co + (size_t)(m + 8) * ldc + n] = make_float2(v2, v3);
            }
        }
    }
}

// ---------------------------------------------------------------------------
// Elementwise fp32 -> (hi, lo) bf16 split
// ---------------------------------------------------------------------------
__global__ __launch_bounds__(256) void split_kernel(
    const float* __restrict__ in, bf16* __restrict__ oh, bf16* __restrict__ ol,
    long long n)
{
    long long i = (long long)blockIdx.x * 256 + threadIdx.x;
    long long stride = (long long)gridDim.x * 256;
    for (; i < n; i += stride) {
        float v = in[i];
        bf16 h = __float2bfloat16(v);
        oh[i] = h;
        ol[i] = __float2bfloat16(v - __bfloat162float(h));
    }
}

// ---------------------------------------------------------------------------
// Row softmax: read fp32 scores, write split bf16 probs.
// ---------------------------------------------------------------------------
__global__ __launch_bounds__(256) void softmax_kernel(
    const float* __restrict__ scores, bf16* __restrict__ ph, bf16* __restrict__ pl)
{
    const float* row = scores + (size_t)blockIdx.x * SEQ;
    bf16* rh = ph + (size_t)blockIdx.x * SEQ;
    bf16* rl = pl + (size_t)blockIdx.x * SEQ;
    const int t = threadIdx.x;

    float v[8];
    float m = -INFINITY;
#pragma unroll
    for (int i = 0; i < 8; i++) {
        v[i] = row[t + i * 256];
        m = fmaxf(m, v[i]);
    }
#pragma unroll
    for (int o = 16; o > 0; o >>= 1)
        m = fmaxf(m, __shfl_xor_sync(0xffffffffu, m, o));

    __shared__ float redmax[8], redsum[8];
    if ((t & 31) == 0) redmax[t >> 5] = m;
    __syncthreads();
    float mm = redmax[0];
#pragma unroll
    for (int i = 1; i < 8; i++) mm = fmaxf(mm, redmax[i]);

    float s = 0.f;
#pragma unroll
    for (int i = 0; i < 8; i++) { v[i] = __expf(v[i] - mm); s += v[i]; }
#pragma unroll
    for (int o = 16; o > 0; o >>= 1)
        s += __shfl_xor_sync(0xffffffffu, s, o);
    if ((t & 31) == 0) redsum[t >> 5] = s;
    __syncthreads();
    float ss = 0.f;
#pragma unroll
    for (int i = 0; i < 8; i++) ss += redsum[i];
    float inv = 1.0f / ss;

#pragma unroll
    for (int i = 0; i < 8; i++) {
        float p = v[i] * inv;
        bf16 h = __float2bfloat16(p);
        rh[t + i * 256] = h;
        rl[t + i * 256] = __float2bfloat16(p - __bfloat162float(h));
    }
}

// ---------------------------------------------------------------------------
// Per-batch transpose of a bf16 (hi, lo) pair: out[c][r] = in[r][c]
// ---------------------------------------------------------------------------
__global__ __launch_bounds__(256) void transpose_pair(
    const bf16* __restrict__ inh, const bf16* __restrict__ inl,
    bf16* __restrict__ outh, bf16* __restrict__ outl,
    int ld_in, int ld_out, long long sIn, long long sOut)
{
    __shared__ bf16 th[32][33];
    __shared__ bf16 tl[32][33];
    inh += (long long)blockIdx.z * sIn;   inl += (long long)blockIdx.z * sIn;
    outh += (long long)blockIdx.z * sOut; outl += (long long)blockIdx.z * sOut;
    const int x0 = blockIdx.x * 32;
    const int y0 = blockIdx.y * 32;

#pragma unroll
    for (int i = threadIdx.y; i < 32; i += 8) {
        th[i][threadIdx.x] = inh[(size_t)(y0 + i) * ld_in + x0 + threadIdx.x];
        tl[i][threadIdx.x] = inl[(size_t)(y0 + i) * ld_in + x0 + threadIdx.x];
    }
    __syncthreads();
#pragma unroll
    for (int i = threadIdx.y; i < 32; i += 8) {
        outh[(size_t)(x0 + i) * ld_out + y0 + threadIdx.x] = th[threadIdx.x][i];
        outl[(size_t)(x0 + i) * ld_out + y0 + threadIdx.x] = tl[threadIdx.x][i];
    }
}

// ---------------------------------------------------------------------------
extern "C" void kernel_launch(void* const* d_in, const int* in_sizes, int n_in,
                              void* d_out, int out_size)
{
    const float* x      = (const float*)d_in[0];   // [B,S,E]
    const float* w_qkv  = (const float*)d_in[1];   // [3H,E]
    const float* w_proj = (const float*)d_in[2];   // [E,H]
    const float* b_proj = (const float*)d_in[3];   // [E]
    float* y = (float*)d_out;                      // [B,S,E]

    bf16 *xh, *xl, *wqh, *wql, *wph, *wpl, *qkvh, *qkvl;
    bf16 *ph, *pl, *vTh, *vTl, *oh, *ol, *oTh, *oTl;
    float* scores;
    cudaGetSymbolAddress((void**)&xh, g_xh);     cudaGetSymbolAddress((void**)&xl, g_xl);
    cudaGetSymbolAddress((void**)&wqh, g_wqh);   cudaGetSymbolAddress((void**)&wql, g_wql);
    cudaGetSymbolAddress((void**)&wph, g_wph);   cudaGetSymbolAddress((void**)&wpl, g_wpl);
    cudaGetSymbolAddress((void**)&qkvh, g_qkvh); cudaGetSymbolAddress((void**)&qkvl, g_qkvl);
    cudaGetSymbolAddress((void**)&scores, g_scores);
    cudaGetSymbolAddress((void**)&ph, g_ph);     cudaGetSymbolAddress((void**)&pl, g_pl);
    cudaGetSymbolAddress((void**)&vTh, g_vTh);   cudaGetSymbolAddress((void**)&vTl, g_vTl);
    cudaGetSymbolAddress((void**)&oh, g_oh);     cudaGetSymbolAddress((void**)&ol, g_ol);
    cudaGetSymbolAddress((void**)&oTh, g_oTh);   cudaGetSymbolAddress((void**)&oTl, g_oTl);

    const int shm = 2 * 98304;   // 192KB
    cudaFuncSetAttribute(tc_gemm<0>, cudaFuncAttributeMaxDynamicSharedMemorySize, shm);
    cudaFuncSetAttribute(tc_gemm<1>, cudaFuncAttributeMaxDynamicSharedMemorySize, shm);
    cudaFuncSetAttribute(tc_gemm<2>, cudaFuncAttributeMaxDynamicSharedMemorySize, shm);

    const long long sQKV = (long long)SEQ * QKV3;
    const long long sSS  = (long long)SEQ * SEQ;
    const long long sSH  = (long long)SEQ * HSZ;
    const long long sHS  = (long long)HSZ * SEQ;

    // 0. split inputs into bf16 (hi, lo)
    split_kernel<<<1024, 256>>>(x,      xh,  xl,  (long long)BS * EMBED);
    split_kernel<<<512,  256>>>(w_qkv,  wqh, wql, (long long)QKV3 * EMBED);
    split_kernel<<<256,  256>>>(w_proj, wph, wpl, (long long)EMBED * HSZ);

    // 1. qkv = x @ w_qkv^T   [8192 x 3072 x 1024], split output. 768 CTAs.
    tc_gemm<2><<<dim3(QKV3 / 256, BS / 128, 1), 512, shm>>>(
        xh, xl, wqh, wql, nullptr, qkvh, qkvl, nullptr,
        EMBED, EMBED, EMBED, QKV3, 0, 0, 0, 1.0f);

    // 2. scores = 0.125 * q @ k^T   4x [2048 x 2048 x 1024]. 512 CTAs.
    tc_gemm<0><<<dim3(SEQ / 256, SEQ / 128, BATCH), 512, shm>>>(
        qkvh, qkvl, qkvh + HSZ, qkvl + HSZ, scores, nullptr, nullptr, nullptr,
        HSZ, QKV3, QKV3, SEQ, sQKV, sQKV, sSS, 0.125f);

    // 3. softmax -> split probs
    softmax_kernel<<<BATCH * SEQ, 256>>>(scores, ph, pl);

    // 4. vT = v^T per batch (v strided inside qkv split arrays)
    transpose_pair<<<dim3(HSZ / 32, SEQ / 32, BATCH), dim3(32, 8)>>>(
        qkvh + 2 * HSZ, qkvl + 2 * HSZ, vTh, vTl, QKV3, SEQ, sQKV, sHS);

    // 5. out = probs @ vT^T   4x [2048 x 1024 x 2048], split output. 256 CTAs.
    tc_gemm<2><<<dim3(HSZ / 256, SEQ / 128, BATCH), 512, shm>>>(
        ph, pl, vTh, vTl, nullptr, oh, ol, nullptr,
        SEQ, SEQ, SEQ, HSZ, sSS, sHS, sSH, 1.0f);

    // 6. scrambling reshape == per-batch transpose (flat re-view)
    transpose_pair<<<dim3(HSZ / 32, SEQ / 32, BATCH), dim3(32, 8)>>>(
        oh, ol, oTh, oTl, HSZ, SEQ, sSH, sHS);

    // 7. y = out2 @ w_proj^T + b   [8192 x 1024 x 1024], fp32 + bias. 256 CTAs.
    tc_gemm<1><<<dim3(EMBED / 256, BS / 128, 1), 512, shm>>>(
        oTh, oTl, wph, wpl, y, nullptr, nullptr, b_proj,
        HSZ, HSZ, HSZ, EMBED, 0, 0, 0, 1.0f);
}

// round 7
// speedup vs baseline: 1.0931x; 1.0931x over previous
#include <cuda_runtime.h>
#include <cuda_bf16.h>
#include <math.h>
#include <stdint.h>

// Problem constants
#define BATCH 4
#define SEQ   2048
#define EMBED 1024
#define HSZ   1024
#define QKV3  3072
#define BS    (BATCH*SEQ)

typedef __nv_bfloat16 bf16;

// Scratch (device globals -- no allocation allowed)
__device__ bf16  g_xh[(size_t)BS * EMBED];
__device__ bf16  g_xl[(size_t)BS * EMBED];
__device__ bf16  g_wqh[(size_t)QKV3 * EMBED];
__device__ bf16  g_wql[(size_t)QKV3 * EMBED];
__device__ bf16  g_wph[(size_t)EMBED * HSZ];
__device__ bf16  g_wpl[(size_t)EMBED * HSZ];
__device__ bf16  g_qkvh[(size_t)BS * QKV3];
__device__ bf16  g_qkvl[(size_t)BS * QKV3];
__device__ float g_scores[(size_t)BATCH * SEQ * SEQ];
__device__ bf16  g_ph[(size_t)BATCH * SEQ * SEQ];
__device__ bf16  g_pl[(size_t)BATCH * SEQ * SEQ];
__device__ bf16  g_vTh[(size_t)BATCH * HSZ * SEQ];
__device__ bf16  g_vTl[(size_t)BATCH * HSZ * SEQ];
__device__ bf16  g_oh[(size_t)BATCH * SEQ * HSZ];
__device__ bf16  g_ol[(size_t)BATCH * SEQ * HSZ];
__device__ bf16  g_oTh[(size_t)BATCH * HSZ * SEQ];
__device__ bf16  g_oTl[(size_t)BATCH * HSZ * SEQ];

// ---------------------------------------------------------------------------
__device__ __forceinline__ uint32_t smem_u32(const void* p) {
    uint32_t a;
    asm("{ .reg .u64 t; cvta.to.shared.u64 t, %1; cvt.u32.u64 %0, t; }"
        : "=r"(a) : "l"(p));
    return a;
}
__device__ __forceinline__ void cp16(uint32_t dst, const void* src) {
    asm volatile("cp.async.cg.shared.global [%0], [%1], 16;"
                 :: "r"(dst), "l"(src));
}
__device__ __forceinline__ void ldsm4(uint32_t* r, uint32_t addr) {
    asm volatile("ldmatrix.sync.aligned.m8n8.x4.shared.b16 {%0,%1,%2,%3}, [%4];"
                 : "=r"(r[0]), "=r"(r[1]), "=r"(r[2]), "=r"(r[3]) : "r"(addr));
}
__device__ __forceinline__ void mma16816(float* c, const uint32_t* a,
                                         const uint32_t* b) {
    asm volatile(
        "mma.sync.aligned.m16n8k16.row.col.f32.bf16.bf16.f32 "
        "{%0,%1,%2,%3}, {%4,%5,%6,%7}, {%8,%9}, {%0,%1,%2,%3};"
        : "+f"(c[0]), "+f"(c[1]), "+f"(c[2]), "+f"(c[3])
        : "r"(a[0]), "r"(a[1]), "r"(a[2]), "r"(a[3]), "r"(b[0]), "r"(b[1]));
}

// ---------------------------------------------------------------------------
// bf16x3 NT GEMM: C[m,n] = alpha * sum_k (Ah+Al)[m,k]*(Bh+Bl)[n,k]  (3 MMAs)
// BM=64, BN=128, BK=64. 256 threads = 8 warps (2m x 4n); warp tile 32x32.
// 4-stage cp.async pipeline (48KB/stage, 192KB), ONE __syncthreads per K-iter,
// explicit fragment double-buffering across k-steps.
// MODE 0: fp32 out; 1: fp32+bias; 2: split bf16 out (Ch,Cl)
// ---------------------------------------------------------------------------
template <int MODE>
__global__ __launch_bounds__(256, 1) void tc_gemm(
    const bf16* __restrict__ Ah, const bf16* __restrict__ Al,
    const bf16* __restrict__ Bh, const bf16* __restrict__ Bl,
    float* __restrict__ C, bf16* __restrict__ Ch, bf16* __restrict__ Cl,
    const float* __restrict__ bias,
    int K, int lda, int ldb, int ldc,
    long long sA, long long sB, long long sC, float alpha)
{
    constexpr uint32_t A_LIMB = 8192u;        // 64 rows x 128B
    constexpr uint32_t B_OFF  = 16384u;
    constexpr uint32_t B_LIMB = 16384u;       // 128 rows x 128B
    constexpr uint32_t STAGE  = 49152u;       // 48KB

    extern __shared__ char dsm[];
    const uint32_t base = smem_u32(dsm);

    const int tid = threadIdx.x;
    const int wid = tid >> 5, lane = tid & 31;
    const int wm = wid >> 2, wn = wid & 3;           // 2 x 4 warps
    const int gid = lane >> 2, tig = lane & 3;

    Ah += (long long)blockIdx.z * sA;  Al += (long long)blockIdx.z * sA;
    Bh += (long long)blockIdx.z * sB;  Bl += (long long)blockIdx.z * sB;
    const long long co = (long long)blockIdx.z * sC;
    const int m0 = blockIdx.y * 64;
    const int n0 = blockIdx.x * 128;

    // ldmatrix per-lane row/chunk decode
    const int rAl = lane & 15,                       cA16 = (lane >> 4) << 4;
    const int rBl = (lane & 7) | ((lane >> 4) << 3), cB16 = ((lane >> 3) & 1) << 4;

    uint32_t rbA[2], swA[2], rbB[2], swB[2];
#pragma unroll
    for (int mt = 0; mt < 2; mt++) {
        int row = wm * 32 + mt * 16 + rAl;
        rbA[mt] = (uint32_t)row << 7;
        swA[mt] = (uint32_t)(row & 7) << 4;
    }
#pragma unroll
    for (int np = 0; np < 2; np++) {
        int row = wn * 32 + np * 16 + rBl;
        rbB[np] = (uint32_t)row << 7;
        swB[np] = (uint32_t)(row & 7) << 4;
    }

    float c[2][4][4];
#pragma unroll
    for (int mt = 0; mt < 2; mt++)
#pragma unroll
        for (int nt = 0; nt < 4; nt++)
#pragma unroll
            for (int i = 0; i < 4; i++) c[mt][nt][i] = 0.f;

    const int NIT = K >> 6;   // BK = 64

    auto load_stage = [&](int it, int s) {
        const uint32_t st = base + (uint32_t)s * STAGE;
        const int c0 = it << 6;
#pragma unroll
        for (int i = 0; i < 2; i++) {              // A: 64 rows x 8 cp16
            int idx = tid + i * 256;
            int r = idx >> 3, ch = idx & 7;
            uint32_t off = ((uint32_t)r << 7) + (((uint32_t)ch << 4) ^ ((uint32_t)(r & 7) << 4));
            cp16(st + off,          Ah + (size_t)(m0 + r) * lda + c0 + ch * 8);
            cp16(st + A_LIMB + off, Al + (size_t)(m0 + r) * lda + c0 + ch * 8);
        }
#pragma unroll
        for (int i = 0; i < 4; i++) {              // B: 128 rows x 8 cp16
            int idx = tid + i * 256;
            int r = idx >> 3, ch = idx & 7;
            uint32_t off = ((uint32_t)r << 7) + (((uint32_t)ch << 4) ^ ((uint32_t)(r & 7) << 4));
            cp16(st + B_OFF + off,          Bh + (size_t)(n0 + r) * ldb + c0 + ch * 8);
            cp16(st + B_OFF + B_LIMB + off, Bl + (size_t)(n0 + r) * ldb + c0 + ch * 8);
        }
        asm volatile("cp.async.commit_group;" ::: "memory");
    };

    load_stage(0, 0);
    load_stage(1, 1);
    load_stage(2, 2);

    // Fragment double buffers
    uint32_t ah[2][2][4], al[2][2][4];   // [buf][mt][reg]
    uint32_t bh[2][2][4], bl[2][2][4];   // [buf][np][reg]

    auto ld_frags = [&](uint32_t st, int ks, int buf) {
        const uint32_t kb = (uint32_t)ks << 5;
#pragma unroll
        for (int mt = 0; mt < 2; mt++) {
            uint32_t a = st + rbA[mt] + ((kb + cA16) ^ swA[mt]);
            ldsm4(ah[buf][mt], a);
            ldsm4(al[buf][mt], a + A_LIMB);
        }
#pragma unroll
        for (int np = 0; np < 2; np++) {
            uint32_t b = st + B_OFF + rbB[np] + ((kb + cB16) ^ swB[np]);
            ldsm4(bh[buf][np], b);
            ldsm4(bl[buf][np], b + B_LIMB);
        }
    };

    auto do_mmas = [&](int buf) {
#pragma unroll
        for (int np = 0; np < 2; np++)
#pragma unroll
            for (int mt = 0; mt < 2; mt++)
#pragma unroll
                for (int h = 0; h < 2; h++) {
                    float* cc = c[mt][np * 2 + h];
                    mma16816(cc, ah[buf][mt], bh[buf][np] + 2 * h);
                    mma16816(cc, ah[buf][mt], bl[buf][np] + 2 * h);
                    mma16816(cc, al[buf][mt], bh[buf][np] + 2 * h);
                }
    };

#pragma unroll 1
    for (int it = 0; it < NIT; it++) {
        asm volatile("cp.async.wait_group 2;" ::: "memory");
        __syncthreads();

        const uint32_t st = base + (uint32_t)(it & 3) * STAGE;
        ld_frags(st, 0, 0);
#pragma unroll
        for (int ks = 0; ks < 4; ks++) {
            if (ks < 3) {
                ld_frags(st, ks + 1, (ks + 1) & 1);   // prefetch next k-step
            } else {
                // overlap next-stage global loads with last k-step's MMAs
                if (it + 3 < NIT) load_stage(it + 3, (it + 3) & 3);
                else asm volatile("cp.async.commit_group;" ::: "memory");
            }
            do_mmas(ks & 1);
        }
        // Stage (it-1)&3 is overwritten only after next iter's sync.
    }

    // Epilogue
#pragma unroll
    for (int mt = 0; mt < 2; mt++) {
#pragma unroll
        for (int nt = 0; nt < 4; nt++) {
            int m = m0 + wm * 32 + mt * 16 + gid;
            int n = n0 + wn * 32 + nt * 8 + tig * 2;
            float v0 = alpha * c[mt][nt][0];
            float v1 = alpha * c[mt][nt][1];
            float v2 = alpha * c[mt][nt][2];
            float v3 = alpha * c[mt][nt][3];
            if (MODE == 1) {
                float b0 = bias[n], b1 = bias[n + 1];
                v0 += b0; v1 += b1; v2 += b0; v3 += b1;
            }
            if (MODE == 2) {
                bf16 h0 = __float2bfloat16(v0);
                bf16 h1 = __float2bfloat16(v1);
                bf16 h2 = __float2bfloat16(v2);
                bf16 h3 = __float2bfloat16(v3);
                bf16 l0 = __float2bfloat16(v0 - __bfloat162float(h0));
                bf16 l1 = __float2bfloat16(v1 - __bfloat162float(h1));
                bf16 l2 = __float2bfloat16(v2 - __bfloat162float(h2));
                bf16 l3 = __float2bfloat16(v3 - __bfloat162float(h3));
                __nv_bfloat162 hh0{h0, h1}, hh1{h2, h3};
                __nv_bfloat162 ll0{l0, l1}, ll1{l2, l3};
                *(__nv_bfloat162*)&Ch[co + (size_t)m * ldc + n]       = hh0;
                *(__nv_bfloat162*)&Ch[co + (size_t)(m + 8) * ldc + n] = hh1;
                *(__nv_bfloat162*)&Cl[co + (size_t)m * ldc + n]       = ll0;
                *(__nv_bfloat162*)&Cl[co + (size_t)(m + 8) * ldc + n] = ll1;
            } else {
                *(float2*)&C[co + (size_t)m * ldc + n]       = make_float2(v0, v1);
                *(float2*)&C[co + (size_t)(m + 8) * ldc + n] = make_float2(v2, v3);
            }
        }
    }
}

// ---------------------------------------------------------------------------
// Elementwise fp32 -> (hi, lo) bf16 split
// ---------------------------------------------------------------------------
__global__ __launch_bounds__(256) void split_kernel(
    const float* __restrict__ in, bf16* __restrict__ oh, bf16* __restrict__ ol,
    long long n)
{
    long long i = (long long)blockIdx.x * 256 + threadIdx.x;
    long long stride = (long long)gridDim.x * 256;
    for (; i < n; i += stride) {
        float v = in[i];
        bf16 h = __float2bfloat16(v);
        oh[i] = h;
        ol[i] = __float2bfloat16(v - __bfloat162float(h));
    }
}

// ---------------------------------------------------------------------------
// Row softmax: read fp32 scores, write split bf16 probs.
// ---------------------------------------------------------------------------
__global__ __launch_bounds__(256) void softmax_kernel(
    const float* __restrict__ scores, bf16* __restrict__ ph, bf16* __restrict__ pl)
{
    const float* row = scores + (size_t)blockIdx.x * SEQ;
    bf16* rh = ph + (size_t)blockIdx.x * SEQ;
    bf16* rl = pl + (size_t)blockIdx.x * SEQ;
    const int t = threadIdx.x;

    float v[8];
    float m = -INFINITY;
#pragma unroll
    for (int i = 0; i < 8; i++) {
        v[i] = row[t + i * 256];
        m = fmaxf(m, v[i]);
    }
#pragma unroll
    for (int o = 16; o > 0; o >>= 1)
        m = fmaxf(m, __shfl_xor_sync(0xffffffffu, m, o));

    __shared__ float redmax[8], redsum[8];
    if ((t & 31) == 0) redmax[t >> 5] = m;
    __syncthreads();
    float mm = redmax[0];
#pragma unroll
    for (int i = 1; i < 8; i++) mm = fmaxf(mm, redmax[i]);

    float s = 0.f;
#pragma unroll
    for (int i = 0; i < 8; i++) { v[i] = __expf(v[i] - mm); s += v[i]; }
#pragma unroll
    for (int o = 16; o > 0; o >>= 1)
        s += __shfl_xor_sync(0xffffffffu, s, o);
    if ((t & 31) == 0) redsum[t >> 5] = s;
    __syncthreads();
    float ss = 0.f;
#pragma unroll
    for (int i = 0; i < 8; i++) ss += redsum[i];
    float inv = 1.0f / ss;

#pragma unroll
    for (int i = 0; i < 8; i++) {
        float p = v[i] * inv;
        bf16 h = __float2bfloat16(p);
        rh[t + i * 256] = h;
        rl[t + i * 256] = __float2bfloat16(p - __bfloat162float(h));
    }
}

// ---------------------------------------------------------------------------
// Per-batch transpose of a bf16 (hi, lo) pair: out[c][r] = in[r][c]
// ---------------------------------------------------------------------------
__global__ __launch_bounds__(256) void transpose_pair(
    const bf16* __restrict__ inh, const bf16* __restrict__ inl,
    bf16* __restrict__ outh, bf16* __restrict__ outl,
    int ld_in, int ld_out, long long sIn, long long sOut)
{
    __shared__ bf16 th[32][33];
    __shared__ bf16 tl[32][33];
    inh += (long long)blockIdx.z * sIn;   inl += (long long)blockIdx.z * sIn;
    outh += (long long)blockIdx.z * sOut; outl += (long long)blockIdx.z * sOut;
    const int x0 = blockIdx.x * 32;
    const int y0 = blockIdx.y * 32;

#pragma unroll
    for (int i = threadIdx.y; i < 32; i += 8) {
        th[i][threadIdx.x] = inh[(size_t)(y0 + i) * ld_in + x0 + threadIdx.x];
        tl[i][threadIdx.x] = inl[(size_t)(y0 + i) * ld_in + x0 + threadIdx.x];
    }
    __syncthreads();
#pragma unroll
    for (int i = threadIdx.y; i < 32; i += 8) {
        outh[(size_t)(x0 + i) * ld_out + y0 + threadIdx.x] = th[threadIdx.x][i];
        outl[(size_t)(x0 + i) * ld_out + y0 + threadIdx.x] = tl[threadIdx.x][i];
    }
}

// ---------------------------------------------------------------------------
extern "C" void kernel_launch(void* const* d_in, const int* in_sizes, int n_in,
                              void* d_out, int out_size)
{
    const float* x      = (const float*)d_in[0];   // [B,S,E]
    const float* w_qkv  = (const float*)d_in[1];   // [3H,E]
    const float* w_proj = (const float*)d_in[2];   // [E,H]
    const float* b_proj = (const float*)d_in[3];   // [E]
    float* y = (float*)d_out;                      // [B,S,E]

    bf16 *xh, *xl, *wqh, *wql, *wph, *wpl, *qkvh, *qkvl;
    bf16 *ph, *pl, *vTh, *vTl, *oh, *ol, *oTh, *oTl;
    float* scores;
    cudaGetSymbolAddress((void**)&xh, g_xh);     cudaGetSymbolAddress((void**)&xl, g_xl);
    cudaGetSymbolAddress((void**)&wqh, g_wqh);   cudaGetSymbolAddress((void**)&wql, g_wql);
    cudaGetSymbolAddress((void**)&wph, g_wph);   cudaGetSymbolAddress((void**)&wpl, g_wpl);
    cudaGetSymbolAddress((void**)&qkvh, g_qkvh); cudaGetSymbolAddress((void**)&qkvl, g_qkvl);
    cudaGetSymbolAddress((void**)&scores, g_scores);
    cudaGetSymbolAddress((void**)&ph, g_ph);     cudaGetSymbolAddress((void**)&pl, g_pl);
    cudaGetSymbolAddress((void**)&vTh, g_vTh);   cudaGetSymbolAddress((void**)&vTl, g_vTl);
    cudaGetSymbolAddress((void**)&oh, g_oh);     cudaGetSymbolAddress((void**)&ol, g_ol);
    cudaGetSymbolAddress((void**)&oTh, g_oTh);   cudaGetSymbolAddress((void**)&oTl, g_oTl);

    const int shm = 4 * 49152;   // 192KB
    cudaFuncSetAttribute(tc_gemm<0>, cudaFuncAttributeMaxDynamicSharedMemorySize, shm);
    cudaFuncSetAttribute(tc_gemm<1>, cudaFuncAttributeMaxDynamicSharedMemorySize, shm);
    cudaFuncSetAttribute(tc_gemm<2>, cudaFuncAttributeMaxDynamicSharedMemorySize, shm);

    const long long sQKV = (long long)SEQ * QKV3;
    const long long sSS  = (long long)SEQ * SEQ;
    const long long sSH  = (long long)SEQ * HSZ;
    const long long sHS  = (long long)HSZ * SEQ;

    // 0. split inputs into bf16 (hi, lo)
    split_kernel<<<1024, 256>>>(x,      xh,  xl,  (long long)BS * EMBED);
    split_kernel<<<512,  256>>>(w_qkv,  wqh, wql, (long long)QKV3 * EMBED);
    split_kernel<<<256,  256>>>(w_proj, wph, wpl, (long long)EMBED * HSZ);

    // 1. qkv = x @ w_qkv^T   [8192 x 3072 x 1024], split output. 3072 CTAs.
    tc_gemm<2><<<dim3(QKV3 / 128, BS / 64, 1), 256, shm>>>(
        xh, xl, wqh, wql, nullptr, qkvh, qkvl, nullptr,
        EMBED, EMBED, EMBED, QKV3, 0, 0, 0, 1.0f);

    // 2. scores = 0.125 * q @ k^T   4x [2048 x 2048 x 1024]. 2048 CTAs.
    tc_gemm<0><<<dim3(SEQ / 128, SEQ / 64, BATCH), 256, shm>>>(
        qkvh, qkvl, qkvh + HSZ, qkvl + HSZ, scores, nullptr, nullptr, nullptr,
        HSZ, QKV3, QKV3, SEQ, sQKV, sQKV, sSS, 0.125f);

    // 3. softmax -> split probs
    softmax_kernel<<<BATCH * SEQ, 256>>>(scores, ph, pl);

    // 4. vT = v^T per batch (v strided inside qkv split arrays)
    transpose_pair<<<dim3(HSZ / 32, SEQ / 32, BATCH), dim3(32, 8)>>>(
        qkvh + 2 * HSZ, qkvl + 2 * HSZ, vTh, vTl, QKV3, SEQ, sQKV, sHS);

    // 5. out = probs @ vT^T   4x [2048 x 1024 x 2048], split output. 1024 CTAs.
    tc_gemm<2><<<dim3(HSZ / 128, SEQ / 64, BATCH), 256, shm>>>(
        ph, pl, vTh, vTl, nullptr, oh, ol, nullptr,
        SEQ, SEQ, SEQ, HSZ, sSS, sHS, sSH, 1.0f);

    // 6. scrambling reshape == per-batch transpose (flat re-view)
    transpose_pair<<<dim3(HSZ / 32, SEQ / 32, BATCH), dim3(32, 8)>>>(
        oh, ol, oTh, oTl, HSZ, SEQ, sSH, sHS);

    // 7. y = out2 @ w_proj^T + b   [8192 x 1024 x 1024], fp32 + bias. 1024 CTAs.
    tc_gemm<1><<<dim3(EMBED / 128, BS / 64, 1), 256, shm>>>(
        oTh, oTl, wph, wpl, y, nullptr, nullptr, b_proj,
        HSZ, HSZ, HSZ, EMBED, 0, 0, 0, 1.0f);
}